// round 12
// baseline (speedup 1.0000x reference)
#include <cuda_runtime.h>
#include <math.h>

// Problem-fixed sizes (from reference setup_inputs)
#define NMAX 50000
#define EMAX 600000
#define TOTMAX (EMAX + NMAX)
#define BGRID 592            // 148 SMs * 4 — co-resident by construction
#define BTHREADS 256
#define CHUNK 85             // ceil(50000 / 592)

// Scratch (static device arrays; no allocation allowed)
__device__ float g_h[NMAX * 128];      // projected features [N, H*D] (fp32)
__device__ float g_asrc[NMAX * 4];     // per-node src attention half (fp32)
__device__ float g_adst[NMAX * 4];     // per-node dst attention half (fp32)
__device__ int2  g_edges[TOTMAX];      // decoded (src, dst) incl. self-loops
__device__ int   g_cnt[NMAX];          // in-degree histogram
__device__ int   g_off[NMAX + 1];      // CSR offsets (exclusive scan)
__device__ int   g_pos[NMAX];          // scatter cursors
__device__ int   g_csr[TOTMAX];        // CSR: src ids grouped by dst
__device__ int   g_bsum[BGRID];        // per-block chunk totals
__device__ unsigned g_bar;             // device-wide barrier counter
__device__ int   g_is64;               // edge_index dtype flag

// ---------------------------------------------------------------------------
// packed fp32x2 FMA (sm_100+; ptxas never emits FFMA2 from C++)
// ---------------------------------------------------------------------------
__device__ __forceinline__ void fma2(unsigned long long& acc,
                                     unsigned long long a,
                                     unsigned long long b) {
    asm("fma.rn.f32x2 %0, %1, %2, %3;" : "=l"(acc) : "l"(a), "l"(b), "l"(acc));
}
__device__ __forceinline__ unsigned long long pack2(float v) {
    unsigned long long r;
    asm("mov.b64 %0, {%1, %1};" : "=l"(r) : "f"(v));
    return r;
}
__device__ __forceinline__ void unpack2(unsigned long long v, float& lo, float& hi) {
    asm("mov.b64 {%0, %1}, %2;" : "=f"(lo), "=f"(hi) : "l"(v));
}

// ---------------------------------------------------------------------------
// device-wide barrier (blocks co-resident by construction)
// ---------------------------------------------------------------------------
__device__ __forceinline__ void grid_barrier(unsigned target) {
    __syncthreads();
    if (threadIdx.x == 0) {
        __threadfence();
        atomicAdd(&g_bar, 1u);
        while (atomicAdd(&g_bar, 0u) < target) { }
    }
    __syncthreads();
}

// ---------------------------------------------------------------------------
// K0: zero counters + barrier + dtype detect
// ---------------------------------------------------------------------------
__global__ void zero_detect_kernel(const int* __restrict__ ei32, int N) {
    int i = blockIdx.x * blockDim.x + threadIdx.x;
    if (i < N) g_cnt[i] = 0;
    if (i == 0) {
        g_bar = 0u;
        int is64 = 1;
        if (ei32[1] != 0) is64 = 0;
        if (ei32[3] != 0) is64 = 0;
        if (ei32[5] != 0) is64 = 0;
        if (ei32[7] != 0) is64 = 0;
        g_is64 = is64;
    }
}

// ---------------------------------------------------------------------------
// Shared GEMM epilogue: attention partials + fp32 store for one row
// ---------------------------------------------------------------------------
__device__ __forceinline__ void gemm_epilogue_row(
    int row, int N, int t, int head, int c0,
    const float acc[8], const float avs[8], const float avd[8]) {
    float ps = 0.0f, pd = 0.0f;
#pragma unroll
    for (int j = 0; j < 8; j++) {
        ps += acc[j] * avs[j];
        pd += acc[j] * avd[j];
    }
    ps += __shfl_xor_sync(0xFFFFFFFFu, ps, 1);
    ps += __shfl_xor_sync(0xFFFFFFFFu, ps, 2);
    pd += __shfl_xor_sync(0xFFFFFFFFu, pd, 1);
    pd += __shfl_xor_sync(0xFFFFFFFFu, pd, 2);

    if (row < N) {
        float4 o0 = {acc[0], acc[1], acc[2], acc[3]};
        float4 o1 = {acc[4], acc[5], acc[6], acc[7]};
        *(float4*)&g_h[(long long)row * 128 + c0]     = o0;
        *(float4*)&g_h[(long long)row * 128 + c0 + 4] = o1;
        if ((t & 3) == 0) {
            g_asrc[row * 4 + head] = ps;
            g_adst[row * 4 + head] = pd;
        }
    }
}

// ---------------------------------------------------------------------------
// K1: smem-staged GEMM. 256 threads, 128-row tile, W (64KB) in dynamic smem.
// ---------------------------------------------------------------------------
__global__ void __launch_bounds__(256) gemm_smem_kernel(
    const float* __restrict__ x, const float* __restrict__ W,
    const float* __restrict__ att_s, const float* __restrict__ att_d, int N) {

    extern __shared__ float sW[];

    int t  = threadIdx.x;
    {
        const float4* Wv = (const float4*)W;
        float4* sWv = (float4*)sW;
#pragma unroll
        for (int i = 0; i < 16; i++)
            sWv[t + i * 256] = Wv[t + i * 256];
    }
    __syncthreads();

    int cg = t & 15;
    int rg = t >> 4;
    int c0 = cg * 8;
    int row0 = blockIdx.x * 128 + rg * 8;

    unsigned long long acc2[8][4];
#pragma unroll
    for (int r = 0; r < 8; r++)
#pragma unroll
        for (int j = 0; j < 4; j++) acc2[r][j] = 0ULL;

    int rrow[8];
#pragma unroll
    for (int r = 0; r < 8; r++) {
        int rr = row0 + r;
        rrow[r] = rr < N ? rr : (N - 1);
    }

    for (int k = 0; k < 128; k += 4) {
        float4 xv[8];
#pragma unroll
        for (int r = 0; r < 8; r++)
            xv[r] = *(const float4*)&x[(long long)rrow[r] * 128 + k];
#pragma unroll
        for (int kk = 0; kk < 4; kk++) {
            ulonglong2 wA = *(const ulonglong2*)&sW[(k + kk) * 128 + c0];
            ulonglong2 wB = *(const ulonglong2*)&sW[(k + kk) * 128 + c0 + 4];
#pragma unroll
            for (int r = 0; r < 8; r++) {
                float xs = (kk == 0) ? xv[r].x : (kk == 1) ? xv[r].y
                          : (kk == 2) ? xv[r].z : xv[r].w;
                unsigned long long xs2 = pack2(xs);
                fma2(acc2[r][0], xs2, wA.x);
                fma2(acc2[r][1], xs2, wA.y);
                fma2(acc2[r][2], xs2, wB.x);
                fma2(acc2[r][3], xs2, wB.y);
            }
        }
    }

    float4 as0 = *(const float4*)&att_s[c0];
    float4 as1 = *(const float4*)&att_s[c0 + 4];
    float4 ad0 = *(const float4*)&att_d[c0];
    float4 ad1 = *(const float4*)&att_d[c0 + 4];
    float avs[8] = {as0.x, as0.y, as0.z, as0.w, as1.x, as1.y, as1.z, as1.w};
    float avd[8] = {ad0.x, ad0.y, ad0.z, ad0.w, ad1.x, ad1.y, ad1.z, ad1.w};
    int head = c0 >> 5;

#pragma unroll
    for (int r = 0; r < 8; r++) {
        float acc[8];
#pragma unroll
        for (int j = 0; j < 4; j++)
            unpack2(acc2[r][j], acc[2 * j], acc[2 * j + 1]);
        gemm_epilogue_row(row0 + r, N, t, head, c0, acc, avs, avd);
    }
}

// ---------------------------------------------------------------------------
// K1 (fallback): register-blocked gemm if smem opt-in failed
// ---------------------------------------------------------------------------
__global__ void __launch_bounds__(128) gemm_kernel(
    const float* __restrict__ x, const float* __restrict__ W,
    const float* __restrict__ att_s, const float* __restrict__ att_d, int N) {

    int t  = threadIdx.x;
    int cg = t & 15;
    int rg = t >> 4;
    int c0 = cg * 8;
    int row0 = blockIdx.x * 32 + rg * 4;

    unsigned long long acc2[4][4];
#pragma unroll
    for (int r = 0; r < 4; r++)
#pragma unroll
        for (int j = 0; j < 4; j++) acc2[r][j] = 0ULL;

    int rrow[4];
#pragma unroll
    for (int r = 0; r < 4; r++) {
        int rr = row0 + r;
        rrow[r] = rr < N ? rr : (N - 1);
    }

    for (int k = 0; k < 128; k += 4) {
        float4 xv[4];
#pragma unroll
        for (int r = 0; r < 4; r++)
            xv[r] = *(const float4*)&x[(long long)rrow[r] * 128 + k];
#pragma unroll
        for (int kk = 0; kk < 4; kk++) {
            ulonglong2 wA = *(const ulonglong2*)&W[(k + kk) * 128 + c0];
            ulonglong2 wB = *(const ulonglong2*)&W[(k + kk) * 128 + c0 + 4];
#pragma unroll
            for (int r = 0; r < 4; r++) {
                float xs = (kk == 0) ? xv[r].x : (kk == 1) ? xv[r].y
                          : (kk == 2) ? xv[r].z : xv[r].w;
                unsigned long long xs2 = pack2(xs);
                fma2(acc2[r][0], xs2, wA.x);
                fma2(acc2[r][1], xs2, wA.y);
                fma2(acc2[r][2], xs2, wB.x);
                fma2(acc2[r][3], xs2, wB.y);
            }
        }
    }

    float4 as0 = *(const float4*)&att_s[c0];
    float4 as1 = *(const float4*)&att_s[c0 + 4];
    float4 ad0 = *(const float4*)&att_d[c0];
    float4 ad1 = *(const float4*)&att_d[c0 + 4];
    float avs[8] = {as0.x, as0.y, as0.z, as0.w, as1.x, as1.y, as1.z, as1.w};
    float avd[8] = {ad0.x, ad0.y, ad0.z, ad0.w, ad1.x, ad1.y, ad1.z, ad1.w};
    int head = c0 >> 5;

#pragma unroll
    for (int r = 0; r < 4; r++) {
        float acc[8];
#pragma unroll
        for (int j = 0; j < 4; j++)
            unpack2(acc2[r][j], acc[2 * j], acc[2 * j + 1]);
        gemm_epilogue_row(row0 + r, N, t, head, c0, acc, avs, avd);
    }
}

// ---------------------------------------------------------------------------
// K2 (fused): hist -> scan -> scatter in one kernel with grid barriers.
// ---------------------------------------------------------------------------
__global__ void __launch_bounds__(BTHREADS) build_kernel(
    const void* __restrict__ ei, int E, int N) {

    int t = threadIdx.x, b = blockIdx.x;
    int gtid = b * BTHREADS + t;
    const int nthr = BGRID * BTHREADS;
    int tot = E + N;

    // ---- Phase 1: decode + histogram ----
    for (int i = gtid; i < tot; i += nthr) {
        int s, d;
        if (i < E) {
            if (g_is64) {
                const long long* p = (const long long*)ei;
                s = (int)p[i];
                d = (int)p[E + i];
            } else {
                const int* p = (const int*)ei;
                s = p[i];
                d = p[E + i];
            }
        } else {
            s = d = i - E;
        }
        g_edges[i] = make_int2(s, d);
        atomicAdd(&g_cnt[d], 1);
    }
    grid_barrier(BGRID);

    // ---- Phase 2: per-block chunk scan ----
    __shared__ int sh_scan[BTHREADS];
    __shared__ int sh_red[BTHREADS];
    int chunk0 = b * CHUNK;
    int v = 0;
    int idx = chunk0 + t;
    if (t < CHUNK && idx < N) v = g_cnt[idx];
    int lane = t & 31, wid = t >> 5;
    int x = v;
#pragma unroll
    for (int o = 1; o < 32; o <<= 1) {
        int y = __shfl_up_sync(0xFFFFFFFFu, x, o);
        if (lane >= o) x += y;
    }
    if (lane == 31) sh_scan[wid] = x;
    __syncthreads();
    if (wid == 0 && lane < 8) {
        int ws = sh_scan[lane];
#pragma unroll
        for (int o = 1; o < 8; o <<= 1) {
            int y = __shfl_up_sync(0xFFu, ws, o);
            if (lane >= o) ws += y;
        }
        sh_scan[lane] = ws;
    }
    __syncthreads();
    int warp_excl = (wid == 0) ? 0 : sh_scan[wid - 1];
    int excl = warp_excl + x - v;
    int btotal = sh_scan[7];
    if (t == 0) g_bsum[b] = btotal;
    grid_barrier(2u * BGRID);

    // ---- Phase 3: every block prefixes the BGRID totals, writes offsets ----
    {
        int before = 0, all = 0;
        for (int j = t; j < BGRID; j += BTHREADS) {
            int bv = g_bsum[j];
            all += bv;
            if (j < b) before += bv;
        }
        sh_scan[t] = before;
        sh_red[t]  = all;
        __syncthreads();
        for (int o = BTHREADS / 2; o > 0; o >>= 1) {
            if (t < o) {
                sh_scan[t] += sh_scan[t + o];
                sh_red[t]  += sh_red[t + o];
            }
            __syncthreads();
        }
        int base = sh_scan[0];
        int grand = sh_red[0];
        if (t < CHUNK && idx < N) {
            int o2 = base + excl;
            g_off[idx] = o2;
            g_pos[idx] = o2;
        }
        if (b == 0 && t == 0) g_off[N] = grand;
    }
    grid_barrier(3u * BGRID);

    // ---- Phase 4: scatter ----
    for (int i = gtid; i < tot; i += nthr) {
        int2 e = g_edges[i];
        int pos = atomicAdd(&g_pos[e.y], 1);
        g_csr[pos] = e.x;
    }
}

// ---------------------------------------------------------------------------
// K3: aggregation, two-phase warp-cooperative (issue-bound -> cut instrs).
// Phase A: lane m computes e[4 heads] for edge m of a 32-edge tile (scalar
// chain amortized ~1 instr/edge), stages (e4, s) in smem, accumulates
// per-lane den partials. Phase B: per edge, broadcast LDS + LDG.128 +
// packed FFMA2 accumulation (2 instrs for 4 dims).
// ---------------------------------------------------------------------------
__global__ void __launch_bounds__(128) agg_kernel(float* __restrict__ out,
                                                  const float* __restrict__ bias,
                                                  int N) {
    __shared__ __align__(16) float sh_e[4][128];   // [warp][edge*4+head]
    __shared__ int sh_s[4][32];                    // [warp][edge]

    int wslot = threadIdx.x >> 5;
    int lane  = threadIdx.x & 31;
    int gw    = (blockIdx.x * blockDim.x + threadIdx.x) >> 5;
    if (gw >= N) return;
    int d    = gw;
    int head = lane >> 3;

    int beg = __ldg(&g_off[d]);
    int end = __ldg(&g_off[d + 1]);

    float4 ad4 = *(const float4*)&g_adst[d * 4];

    unsigned long long accA = 0ULL, accB = 0ULL;   // (a0,a1),(a2,a3)
    float dp0 = 0.f, dp1 = 0.f, dp2 = 0.f, dp3 = 0.f;  // per-lane den partials

    for (int j0 = beg; j0 < end; j0 += 32) {
        int cnt = min(32, end - j0);

        // ---- Phase A ----
        if (lane < cnt) {
            int s = __ldg(&g_csr[j0 + lane]);
            float4 as4 = *(const float4*)&g_asrc[s * 4];
            float l0 = as4.x + ad4.x;
            float l1 = as4.y + ad4.y;
            float l2 = as4.z + ad4.z;
            float l3 = as4.w + ad4.w;
            l0 = fmaxf(l0, 0.2f * l0);
            l1 = fmaxf(l1, 0.2f * l1);
            l2 = fmaxf(l2, 0.2f * l2);
            l3 = fmaxf(l3, 0.2f * l3);
            float e0 = __expf(l0);
            float e1 = __expf(l1);
            float e2 = __expf(l2);
            float e3 = __expf(l3);
            dp0 += e0; dp1 += e1; dp2 += e2; dp3 += e3;
            sh_s[wslot][lane] = s;
            *(float4*)&sh_e[wslot][lane * 4] = make_float4(e0, e1, e2, e3);
        }
        __syncwarp();

        // ---- Phase B ----
        for (int m = 0; m < cnt; m++) {
            int s = sh_s[wslot][m];                       // broadcast LDS
            float e = sh_e[wslot][m * 4 + head];          // broadcast LDS
            unsigned long long e2p = pack2(e);
            ulonglong2 hv = *(const ulonglong2*)&g_h[(long long)s * 128 + lane * 4];
            fma2(accA, e2p, hv.x);
            fma2(accB, e2p, hv.y);
        }
        __syncwarp();
    }

    // reduce den partials (per head) across the warp
    float den[4] = {dp0, dp1, dp2, dp3};
#pragma unroll
    for (int h = 0; h < 4; h++) {
        float v = den[h];
#pragma unroll
        for (int o = 16; o >= 1; o >>= 1)
            v += __shfl_xor_sync(0xFFFFFFFFu, v, o);
        den[h] = v;
    }
    float dh = (head == 0) ? den[0] : (head == 1) ? den[1]
             : (head == 2) ? den[2] : den[3];
    float inv = 1.0f / dh;

    float a0, a1, a2, a3;
    unpack2(accA, a0, a1);
    unpack2(accB, a2, a3);

    float4 bv = *(const float4*)&bias[lane * 4];
    float4 ov;
    ov.x = tanhf(a0 * inv + bv.x);
    ov.y = tanhf(a1 * inv + bv.y);
    ov.z = tanhf(a2 * inv + bv.z);
    ov.w = tanhf(a3 * inv + bv.w);
    *(float4*)&out[(long long)d * 128 + lane * 4] = ov;
}

// ---------------------------------------------------------------------------
// Host-side one-time setup: side stream/events + smem opt-in for gemm.
// ---------------------------------------------------------------------------
#define GEMM_SMEM_BYTES (128 * 128 * sizeof(float))
static cudaStream_t g_s1 = 0;
static cudaEvent_t  g_e0 = 0, g_e1 = 0;
static bool g_forked = false;
static bool g_smem_ok = false;
static struct SideStreamInit {
    SideStreamInit() {
        bool ok = true;
        ok &= (cudaStreamCreateWithFlags(&g_s1, cudaStreamNonBlocking) == cudaSuccess);
        ok &= (cudaEventCreateWithFlags(&g_e0, cudaEventDisableTiming) == cudaSuccess);
        ok &= (cudaEventCreateWithFlags(&g_e1, cudaEventDisableTiming) == cudaSuccess);
        g_forked = ok;
        g_smem_ok = (cudaFuncSetAttribute(gemm_smem_kernel,
                        cudaFuncAttributeMaxDynamicSharedMemorySize,
                        (int)GEMM_SMEM_BYTES) == cudaSuccess);
    }
} g_side_stream_init;

static inline void launch_gemm(const float* x, const float* W,
                               const float* att_s, const float* att_d,
                               int N, cudaStream_t st) {
    if (g_smem_ok)
        gemm_smem_kernel<<<(N + 127) / 128, 256, GEMM_SMEM_BYTES, st>>>(
            x, W, att_s, att_d, N);
    else
        gemm_kernel<<<(N + 31) / 32, 128, 0, st>>>(x, W, att_s, att_d, N);
}

// ---------------------------------------------------------------------------
extern "C" void kernel_launch(void* const* d_in, const int* in_sizes, int n_in,
                              void* d_out, int out_size) {
    const float* x     = (const float*)d_in[0];
    const void*  ei    = d_in[1];
    const float* W     = (const float*)d_in[2];
    const float* att_s = (const float*)d_in[3];
    const float* att_d = (const float*)d_in[4];
    const float* bias  = (const float*)d_in[5];
    float* out = (float*)d_out;

    int N = in_sizes[0] / 128;
    int E = in_sizes[1] / 2;

    if (g_forked) {
        cudaEventRecord(g_e0, 0);
        cudaStreamWaitEvent(g_s1, g_e0, 0);
        launch_gemm(x, W, att_s, att_d, N, g_s1);
        cudaEventRecord(g_e1, g_s1);

        zero_detect_kernel<<<(N + 255) / 256, 256>>>((const int*)ei, N);
        build_kernel<<<BGRID, BTHREADS>>>(ei, E, N);

        cudaStreamWaitEvent(0, g_e1, 0);
        agg_kernel<<<(N * 32 + 127) / 128, 128>>>(out, bias, N);
    } else {
        zero_detect_kernel<<<(N + 255) / 256, 256>>>((const int*)ei, N);
        launch_gemm(x, W, att_s, att_d, N, 0);
        build_kernel<<<BGRID, BTHREADS>>>(ei, E, N);
        agg_kernel<<<(N * 32 + 127) / 128, 128>>>(out, bias, N);
    }
}

// round 13
// speedup vs baseline: 1.0264x; 1.0264x over previous
#include <cuda_runtime.h>
#include <math.h>

// Problem-fixed sizes (from reference setup_inputs)
#define NMAX 50000
#define EMAX 600000
#define TOTMAX (EMAX + NMAX)
#define BGRID 592            // 148 SMs * 4 — co-resident by construction
#define BTHREADS 256
#define CHUNK 85             // ceil(50000 / 592)

// Scratch (static device arrays; no allocation allowed)
__device__ float g_h[NMAX * 128];      // projected features [N, H*D] (fp32)
__device__ float g_asrc[NMAX * 4];     // per-node src attention half (fp32)
__device__ float g_adst[NMAX * 4];     // per-node dst attention half (fp32)
__device__ int2  g_edges[TOTMAX];      // decoded (src, dst) incl. self-loops
__device__ int   g_cnt[NMAX];          // in-degree histogram
__device__ int   g_off[NMAX + 1];      // CSR offsets (exclusive scan)
__device__ int   g_pos[NMAX];          // scatter cursors
__device__ int   g_csr[TOTMAX];        // CSR: src ids grouped by dst
__device__ int   g_bsum[BGRID];        // per-block chunk totals
__device__ unsigned g_bar;             // device-wide barrier counter
__device__ int   g_is64;               // edge_index dtype flag

// ---------------------------------------------------------------------------
// packed fp32x2 FMA (sm_100+; ptxas never emits FFMA2 from C++)
// ---------------------------------------------------------------------------
__device__ __forceinline__ void fma2(unsigned long long& acc,
                                     unsigned long long a,
                                     unsigned long long b) {
    asm("fma.rn.f32x2 %0, %1, %2, %3;" : "=l"(acc) : "l"(a), "l"(b), "l"(acc));
}
__device__ __forceinline__ unsigned long long pack2(float v) {
    unsigned long long r;
    asm("mov.b64 %0, {%1, %1};" : "=l"(r) : "f"(v));
    return r;
}
__device__ __forceinline__ void unpack2(unsigned long long v, float& lo, float& hi) {
    asm("mov.b64 {%0, %1}, %2;" : "=f"(lo), "=f"(hi) : "l"(v));
}

// fast tanh: clamped exp identity; __expf/__fdividef rel err ~1e-6
__device__ __forceinline__ float fast_tanh(float x) {
    x = fminf(fmaxf(x, -9.0f), 9.0f);
    float t = __expf(2.0f * x);
    return (t - 1.0f) * __fdividef(1.0f, t + 1.0f);
}

// ---------------------------------------------------------------------------
// device-wide barrier (blocks co-resident by construction)
// ---------------------------------------------------------------------------
__device__ __forceinline__ void grid_barrier(unsigned target) {
    __syncthreads();
    if (threadIdx.x == 0) {
        __threadfence();
        atomicAdd(&g_bar, 1u);
        while (atomicAdd(&g_bar, 0u) < target) { }
    }
    __syncthreads();
}

// ---------------------------------------------------------------------------
// K0: zero counters + barrier + dtype detect
// ---------------------------------------------------------------------------
__global__ void zero_detect_kernel(const int* __restrict__ ei32, int N) {
    int i = blockIdx.x * blockDim.x + threadIdx.x;
    if (i < N) g_cnt[i] = 0;
    if (i == 0) {
        g_bar = 0u;
        int is64 = 1;
        if (ei32[1] != 0) is64 = 0;
        if (ei32[3] != 0) is64 = 0;
        if (ei32[5] != 0) is64 = 0;
        if (ei32[7] != 0) is64 = 0;
        g_is64 = is64;
    }
}

// ---------------------------------------------------------------------------
// Shared GEMM epilogue: attention partials + fp32 store for one row
// ---------------------------------------------------------------------------
__device__ __forceinline__ void gemm_epilogue_row(
    int row, int N, int t, int head, int c0,
    const float acc[8], const float avs[8], const float avd[8]) {
    float ps = 0.0f, pd = 0.0f;
#pragma unroll
    for (int j = 0; j < 8; j++) {
        ps += acc[j] * avs[j];
        pd += acc[j] * avd[j];
    }
    ps += __shfl_xor_sync(0xFFFFFFFFu, ps, 1);
    ps += __shfl_xor_sync(0xFFFFFFFFu, ps, 2);
    pd += __shfl_xor_sync(0xFFFFFFFFu, pd, 1);
    pd += __shfl_xor_sync(0xFFFFFFFFu, pd, 2);

    if (row < N) {
        float4 o0 = {acc[0], acc[1], acc[2], acc[3]};
        float4 o1 = {acc[4], acc[5], acc[6], acc[7]};
        *(float4*)&g_h[(long long)row * 128 + c0]     = o0;
        *(float4*)&g_h[(long long)row * 128 + c0 + 4] = o1;
        if ((t & 3) == 0) {
            g_asrc[row * 4 + head] = ps;
            g_adst[row * 4 + head] = pd;
        }
    }
}

// ---------------------------------------------------------------------------
// K1: smem-staged GEMM. 256 threads, 128-row tile, W (64KB) in dynamic smem.
// ---------------------------------------------------------------------------
__global__ void __launch_bounds__(256) gemm_smem_kernel(
    const float* __restrict__ x, const float* __restrict__ W,
    const float* __restrict__ att_s, const float* __restrict__ att_d, int N) {

    extern __shared__ float sW[];

    int t  = threadIdx.x;
    {
        const float4* Wv = (const float4*)W;
        float4* sWv = (float4*)sW;
#pragma unroll
        for (int i = 0; i < 16; i++)
            sWv[t + i * 256] = Wv[t + i * 256];
    }
    __syncthreads();

    int cg = t & 15;
    int rg = t >> 4;
    int c0 = cg * 8;
    int row0 = blockIdx.x * 128 + rg * 8;

    unsigned long long acc2[8][4];
#pragma unroll
    for (int r = 0; r < 8; r++)
#pragma unroll
        for (int j = 0; j < 4; j++) acc2[r][j] = 0ULL;

    int rrow[8];
#pragma unroll
    for (int r = 0; r < 8; r++) {
        int rr = row0 + r;
        rrow[r] = rr < N ? rr : (N - 1);
    }

    for (int k = 0; k < 128; k += 4) {
        float4 xv[8];
#pragma unroll
        for (int r = 0; r < 8; r++)
            xv[r] = *(const float4*)&x[(long long)rrow[r] * 128 + k];
#pragma unroll
        for (int kk = 0; kk < 4; kk++) {
            ulonglong2 wA = *(const ulonglong2*)&sW[(k + kk) * 128 + c0];
            ulonglong2 wB = *(const ulonglong2*)&sW[(k + kk) * 128 + c0 + 4];
#pragma unroll
            for (int r = 0; r < 8; r++) {
                float xs = (kk == 0) ? xv[r].x : (kk == 1) ? xv[r].y
                          : (kk == 2) ? xv[r].z : xv[r].w;
                unsigned long long xs2 = pack2(xs);
                fma2(acc2[r][0], xs2, wA.x);
                fma2(acc2[r][1], xs2, wA.y);
                fma2(acc2[r][2], xs2, wB.x);
                fma2(acc2[r][3], xs2, wB.y);
            }
        }
    }

    float4 as0 = *(const float4*)&att_s[c0];
    float4 as1 = *(const float4*)&att_s[c0 + 4];
    float4 ad0 = *(const float4*)&att_d[c0];
    float4 ad1 = *(const float4*)&att_d[c0 + 4];
    float avs[8] = {as0.x, as0.y, as0.z, as0.w, as1.x, as1.y, as1.z, as1.w};
    float avd[8] = {ad0.x, ad0.y, ad0.z, ad0.w, ad1.x, ad1.y, ad1.z, ad1.w};
    int head = c0 >> 5;

#pragma unroll
    for (int r = 0; r < 8; r++) {
        float acc[8];
#pragma unroll
        for (int j = 0; j < 4; j++)
            unpack2(acc2[r][j], acc[2 * j], acc[2 * j + 1]);
        gemm_epilogue_row(row0 + r, N, t, head, c0, acc, avs, avd);
    }
}

// ---------------------------------------------------------------------------
// K1 (fallback): register-blocked gemm if smem opt-in failed
// ---------------------------------------------------------------------------
__global__ void __launch_bounds__(128) gemm_kernel(
    const float* __restrict__ x, const float* __restrict__ W,
    const float* __restrict__ att_s, const float* __restrict__ att_d, int N) {

    int t  = threadIdx.x;
    int cg = t & 15;
    int rg = t >> 4;
    int c0 = cg * 8;
    int row0 = blockIdx.x * 32 + rg * 4;

    unsigned long long acc2[4][4];
#pragma unroll
    for (int r = 0; r < 4; r++)
#pragma unroll
        for (int j = 0; j < 4; j++) acc2[r][j] = 0ULL;

    int rrow[4];
#pragma unroll
    for (int r = 0; r < 4; r++) {
        int rr = row0 + r;
        rrow[r] = rr < N ? rr : (N - 1);
    }

    for (int k = 0; k < 128; k += 4) {
        float4 xv[4];
#pragma unroll
        for (int r = 0; r < 4; r++)
            xv[r] = *(const float4*)&x[(long long)rrow[r] * 128 + k];
#pragma unroll
        for (int kk = 0; kk < 4; kk++) {
            ulonglong2 wA = *(const ulonglong2*)&W[(k + kk) * 128 + c0];
            ulonglong2 wB = *(const ulonglong2*)&W[(k + kk) * 128 + c0 + 4];
#pragma unroll
            for (int r = 0; r < 4; r++) {
                float xs = (kk == 0) ? xv[r].x : (kk == 1) ? xv[r].y
                          : (kk == 2) ? xv[r].z : xv[r].w;
                unsigned long long xs2 = pack2(xs);
                fma2(acc2[r][0], xs2, wA.x);
                fma2(acc2[r][1], xs2, wA.y);
                fma2(acc2[r][2], xs2, wB.x);
                fma2(acc2[r][3], xs2, wB.y);
            }
        }
    }

    float4 as0 = *(const float4*)&att_s[c0];
    float4 as1 = *(const float4*)&att_s[c0 + 4];
    float4 ad0 = *(const float4*)&att_d[c0];
    float4 ad1 = *(const float4*)&att_d[c0 + 4];
    float avs[8] = {as0.x, as0.y, as0.z, as0.w, as1.x, as1.y, as1.z, as1.w};
    float avd[8] = {ad0.x, ad0.y, ad0.z, ad0.w, ad1.x, ad1.y, ad1.z, ad1.w};
    int head = c0 >> 5;

#pragma unroll
    for (int r = 0; r < 4; r++) {
        float acc[8];
#pragma unroll
        for (int j = 0; j < 4; j++)
            unpack2(acc2[r][j], acc[2 * j], acc[2 * j + 1]);
        gemm_epilogue_row(row0 + r, N, t, head, c0, acc, avs, avd);
    }
}

// ---------------------------------------------------------------------------
// K2 (fused): hist -> scan -> scatter in one kernel with grid barriers.
// ---------------------------------------------------------------------------
__global__ void __launch_bounds__(BTHREADS) build_kernel(
    const void* __restrict__ ei, int E, int N) {

    int t = threadIdx.x, b = blockIdx.x;
    int gtid = b * BTHREADS + t;
    const int nthr = BGRID * BTHREADS;
    int tot = E + N;

    // ---- Phase 1: decode + histogram ----
    for (int i = gtid; i < tot; i += nthr) {
        int s, d;
        if (i < E) {
            if (g_is64) {
                const long long* p = (const long long*)ei;
                s = (int)p[i];
                d = (int)p[E + i];
            } else {
                const int* p = (const int*)ei;
                s = p[i];
                d = p[E + i];
            }
        } else {
            s = d = i - E;
        }
        g_edges[i] = make_int2(s, d);
        atomicAdd(&g_cnt[d], 1);
    }
    grid_barrier(BGRID);

    // ---- Phase 2: per-block chunk scan ----
    __shared__ int sh_scan[BTHREADS];
    __shared__ int sh_red[BTHREADS];
    int chunk0 = b * CHUNK;
    int v = 0;
    int idx = chunk0 + t;
    if (t < CHUNK && idx < N) v = g_cnt[idx];
    int lane = t & 31, wid = t >> 5;
    int x = v;
#pragma unroll
    for (int o = 1; o < 32; o <<= 1) {
        int y = __shfl_up_sync(0xFFFFFFFFu, x, o);
        if (lane >= o) x += y;
    }
    if (lane == 31) sh_scan[wid] = x;
    __syncthreads();
    if (wid == 0 && lane < 8) {
        int ws = sh_scan[lane];
#pragma unroll
        for (int o = 1; o < 8; o <<= 1) {
            int y = __shfl_up_sync(0xFFu, ws, o);
            if (lane >= o) ws += y;
        }
        sh_scan[lane] = ws;
    }
    __syncthreads();
    int warp_excl = (wid == 0) ? 0 : sh_scan[wid - 1];
    int excl = warp_excl + x - v;
    int btotal = sh_scan[7];
    if (t == 0) g_bsum[b] = btotal;
    grid_barrier(2u * BGRID);

    // ---- Phase 3: every block prefixes the BGRID totals, writes offsets ----
    {
        int before = 0, all = 0;
        for (int j = t; j < BGRID; j += BTHREADS) {
            int bv = g_bsum[j];
            all += bv;
            if (j < b) before += bv;
        }
        sh_scan[t] = before;
        sh_red[t]  = all;
        __syncthreads();
        for (int o = BTHREADS / 2; o > 0; o >>= 1) {
            if (t < o) {
                sh_scan[t] += sh_scan[t + o];
                sh_red[t]  += sh_red[t + o];
            }
            __syncthreads();
        }
        int base = sh_scan[0];
        int grand = sh_red[0];
        if (t < CHUNK && idx < N) {
            int o2 = base + excl;
            g_off[idx] = o2;
            g_pos[idx] = o2;
        }
        if (b == 0 && t == 0) g_off[N] = grand;
    }
    grid_barrier(3u * BGRID);

    // ---- Phase 4: scatter ----
    for (int i = gtid; i < tot; i += nthr) {
        int2 e = g_edges[i];
        int pos = atomicAdd(&g_pos[e.y], 1);
        g_csr[pos] = e.x;
    }
}

// ---------------------------------------------------------------------------
// K3: aggregation. One warp per destination node, simple prefetch loop
// (proven best shape), fp32 h + packed FFMA2 accumulation, fast-tanh epilogue.
// ---------------------------------------------------------------------------
__global__ void __launch_bounds__(128) agg_kernel(float* __restrict__ out,
                                                  const float* __restrict__ bias,
                                                  int N) {
    int gw   = (blockIdx.x * blockDim.x + threadIdx.x) >> 5;
    int lane = threadIdx.x & 31;
    if (gw >= N) return;
    int d    = gw;
    int head = lane >> 3;

    int beg = __ldg(&g_off[d]);
    int end = __ldg(&g_off[d + 1]);

    float adv = g_adst[d * 4 + head];
    float den = 0.0f;
    unsigned long long accA = 0ULL, accB = 0ULL;

    int s = (beg < end) ? __ldg(&g_csr[beg]) : 0;
    for (int j = beg; j < end; j++) {
        float as = __ldg(&g_asrc[s * 4 + head]);
        ulonglong2 hv = *(const ulonglong2*)&g_h[(long long)s * 128 + lane * 4];
        int s_next = (j + 1 < end) ? __ldg(&g_csr[j + 1]) : 0;

        float l = as + adv;
        l = fmaxf(l, 0.2f * l);
        float e = __expf(l);
        den += e;
        unsigned long long e2 = pack2(e);
        fma2(accA, e2, hv.x);
        fma2(accB, e2, hv.y);
        s = s_next;
    }

    float inv = __fdividef(1.0f, den);
    float a0, a1, a2, a3;
    unpack2(accA, a0, a1);
    unpack2(accB, a2, a3);

    float4 bv = *(const float4*)&bias[lane * 4];
    float4 ov;
    ov.x = fast_tanh(a0 * inv + bv.x);
    ov.y = fast_tanh(a1 * inv + bv.y);
    ov.z = fast_tanh(a2 * inv + bv.z);
    ov.w = fast_tanh(a3 * inv + bv.w);
    *(float4*)&out[(long long)d * 128 + lane * 4] = ov;
}

// ---------------------------------------------------------------------------
// Host-side one-time setup: side stream/events + smem opt-in for gemm.
// ---------------------------------------------------------------------------
#define GEMM_SMEM_BYTES (128 * 128 * sizeof(float))
static cudaStream_t g_s1 = 0;
static cudaEvent_t  g_e0 = 0, g_e1 = 0;
static bool g_forked = false;
static bool g_smem_ok = false;
static struct SideStreamInit {
    SideStreamInit() {
        bool ok = true;
        ok &= (cudaStreamCreateWithFlags(&g_s1, cudaStreamNonBlocking) == cudaSuccess);
        ok &= (cudaEventCreateWithFlags(&g_e0, cudaEventDisableTiming) == cudaSuccess);
        ok &= (cudaEventCreateWithFlags(&g_e1, cudaEventDisableTiming) == cudaSuccess);
        g_forked = ok;
        g_smem_ok = (cudaFuncSetAttribute(gemm_smem_kernel,
                        cudaFuncAttributeMaxDynamicSharedMemorySize,
                        (int)GEMM_SMEM_BYTES) == cudaSuccess);
    }
} g_side_stream_init;

static inline void launch_gemm(const float* x, const float* W,
                               const float* att_s, const float* att_d,
                               int N, cudaStream_t st) {
    if (g_smem_ok)
        gemm_smem_kernel<<<(N + 127) / 128, 256, GEMM_SMEM_BYTES, st>>>(
            x, W, att_s, att_d, N);
    else
        gemm_kernel<<<(N + 31) / 32, 128, 0, st>>>(x, W, att_s, att_d, N);
}

// ---------------------------------------------------------------------------
extern "C" void kernel_launch(void* const* d_in, const int* in_sizes, int n_in,
                              void* d_out, int out_size) {
    const float* x     = (const float*)d_in[0];
    const void*  ei    = d_in[1];
    const float* W     = (const float*)d_in[2];
    const float* att_s = (const float*)d_in[3];
    const float* att_d = (const float*)d_in[4];
    const float* bias  = (const float*)d_in[5];
    float* out = (float*)d_out;

    int N = in_sizes[0] / 128;
    int E = in_sizes[1] / 2;

    if (g_forked) {
        cudaEventRecord(g_e0, 0);
        cudaStreamWaitEvent(g_s1, g_e0, 0);
        launch_gemm(x, W, att_s, att_d, N, g_s1);
        cudaEventRecord(g_e1, g_s1);

        zero_detect_kernel<<<(N + 255) / 256, 256>>>((const int*)ei, N);
        build_kernel<<<BGRID, BTHREADS>>>(ei, E, N);

        cudaStreamWaitEvent(0, g_e1, 0);
        agg_kernel<<<(N * 32 + 127) / 128, 128>>>(out, bias, N);
    } else {
        zero_detect_kernel<<<(N + 255) / 256, 256>>>((const int*)ei, N);
        launch_gemm(x, W, att_s, att_d, N, 0);
        build_kernel<<<BGRID, BTHREADS>>>(ei, E, N);
        agg_kernel<<<(N * 32 + 127) / 128, 128>>>(out, bias, N);
    }
}